// round 14
// baseline (speedup 1.0000x reference)
#include <cuda_runtime.h>

// image [1,128,128,512] f32 NHWC, RoI [N,4] f32 (cx,cy,w,h), POOL=7, STRIDE=16.
#define POOL    7
#define HH      128
#define WW      128
#define CC      512
#define NMAX    1024
#define CPC_MAX 96          // max cells per CTA chunk (smem: 96*32B = 3KB)

// ---------------------------------------------------------------------------
// Single fused kernel, one wave of persistent CTAs (148 x 6 = 888).
//   Phase A: threads 0..cpc-1 compute their cell's bilinear params from the
//            RoI table into smem (math identical to reference).
//   Phase B: register double-buffered sweep (R13 body, compiles to 37 regs):
//            issue next cell's 4 corner LDG.128, then blend+store the
//            current cell's loads from the previous iteration.
// Change vs R13: __launch_bounds__(256, 6) + wave sized for 6 CTAs/SM.
// The body fits the 42-reg cap unchanged; we buy back 50% more resident
// warps (32 -> 48 per SM), which across R9..R13 is the variable that
// tracks kernel time (occ72% -> 29.6us vs occ45% -> 30.8us).
// ---------------------------------------------------------------------------
__global__ __launch_bounds__(256, 6)
void roi_pool_fused(const float* __restrict__ img, const float* __restrict__ roi,
                    float* __restrict__ out, int totalCells, int cpc)
{
    __shared__ int4   s_off[CPC_MAX];   // corner offsets, float4 units
    __shared__ float4 s_w  [CPC_MAX];   // bilinear weights

    const int base = blockIdx.x * cpc;
    const int tid  = threadIdx.x;

    if (base >= totalCells) return;

    // ---------------- Phase A: per-cell params into smem ----------------
    if (tid < cpc) {
        int cell = base + tid;
        if (cell < totalCells) {
            int n   = cell / (POOL * POOL);
            int rem = cell - n * (POOL * POOL);
            int py  = rem / POOL;
            int px  = rem - py * POOL;

            const float inv_stride = 1.0f / 16.0f;
            float cx = roi[n * 4 + 0];
            float cy = roi[n * 4 + 1];
            float w  = roi[n * 4 + 2];
            float h  = roi[n * 4 + 3];

            float r  = rintf((cx - 0.5f * w) * inv_stride);   // x start (col)
            float c  = rintf((cy - 0.5f * h) * inv_stride);   // y start (row)
            float wq = fmaxf(rintf(w * inv_stride), 1.0f);
            float hq = fmaxf(rintf(h * inv_stride), 1.0f);

            // y axis (rows, limit HH)
            float gy  = (py + 0.5f) / (float)POOL;
            float sy  = fminf(fmaxf(gy * hq - 0.5f, 0.0f), hq - 1.0f);
            float fy0 = floorf(sy);
            float ly  = sy - fy0;
            float fy1 = fminf(fy0 + 1.0f, hq - 1.0f);
            int iy0 = (int)fminf(fmaxf(c + fy0, 0.0f), (float)(HH - 1));
            int iy1 = (int)fminf(fmaxf(c + fy1, 0.0f), (float)(HH - 1));

            // x axis (cols, limit WW)
            float gx  = (px + 0.5f) / (float)POOL;
            float sx  = fminf(fmaxf(gx * wq - 0.5f, 0.0f), wq - 1.0f);
            float fx0 = floorf(sx);
            float lx  = sx - fx0;
            float fx1 = fminf(fx0 + 1.0f, wq - 1.0f);
            int ix0 = (int)fminf(fmaxf(r + fx0, 0.0f), (float)(WW - 1));
            int ix1 = (int)fminf(fmaxf(r + fx1, 0.0f), (float)(WW - 1));

            s_off[tid] = make_int4((iy0 * WW + ix0) * (CC / 4),
                                   (iy0 * WW + ix1) * (CC / 4),
                                   (iy1 * WW + ix0) * (CC / 4),
                                   (iy1 * WW + ix1) * (CC / 4));
            s_w[tid] = make_float4((1.0f - ly) * (1.0f - lx),
                                   (1.0f - ly) * lx,
                                   ly * (1.0f - lx),
                                   ly * lx);
        }
    }
    __syncthreads();

    // ---------------- Phase B: double-buffered data sweep ----------------
    const int lane = tid & 127;         // float4 lane within cell
    const int half = tid >> 7;          // which of 2 interleaved cells

    int nIter = totalCells - base;
    if (nIter > cpc) nIter = cpc;

    const float4* __restrict__ img4 = (const float4*)img;
    float4*       __restrict__ out4 = (float4*)out;

    int i = half;
    if (i >= nIter) return;

    // Prime: params + data loads for first owned cell.
    int4   o0 = s_off[i];
    float4 w0 = s_w[i];
    float4 a0 = __ldg(img4 + o0.x + lane);
    float4 b0 = __ldg(img4 + o0.y + lane);
    float4 c0 = __ldg(img4 + o0.z + lane);
    float4 d0 = __ldg(img4 + o0.w + lane);

    while (true) {
        int  nx   = i + 2;
        bool more = nx < nIter;

        // Issue NEXT cell's loads first — consumed next iteration.
        int4   o1;
        float4 w1;
        float4 a1, b1, c1, d1;
        if (more) {
            o1 = s_off[nx];
            w1 = s_w[nx];
            a1 = __ldg(img4 + o1.x + lane);
            b1 = __ldg(img4 + o1.y + lane);
            c1 = __ldg(img4 + o1.z + lane);
            d1 = __ldg(img4 + o1.w + lane);
        }

        // Consume CURRENT cell (loads issued one full iteration ago).
        float4 r;
        r.x = w0.x * a0.x + w0.y * b0.x + w0.z * c0.x + w0.w * d0.x;
        r.y = w0.x * a0.y + w0.y * b0.y + w0.z * c0.y + w0.w * d0.y;
        r.z = w0.x * a0.z + w0.y * b0.z + w0.z * c0.z + w0.w * d0.z;
        r.w = w0.x * a0.w + w0.y * b0.w + w0.z * c0.w + w0.w * d0.w;

        __stcs(out4 + (size_t)(base + i) * (CC / 4) + lane, r);

        if (!more) break;
        i = nx;
        o0 = o1; w0 = w1;
        a0 = a1; b0 = b1; c0 = c1; d0 = d1;
    }
}

extern "C" void kernel_launch(void* const* d_in, const int* in_sizes, int n_in,
                              void* d_out, int out_size)
{
    const float* img = (const float*)d_in[0];   // [1,128,128,512] f32
    const float* roi = (const float*)d_in[1];   // [N,4] f32
    float*       out = (float*)d_out;           // [1,N,7,7,512] f32

    int N = in_sizes[1] / 4;
    if (N > NMAX) N = NMAX;
    int totalCells = N * POOL * POOL;

    int wave = 148 * 6;                          // one wave at occ=6
    int cpc  = (totalCells + wave - 1) / wave;   // cells per CTA chunk
    if (cpc > CPC_MAX) cpc = CPC_MAX;
    int grid = (totalCells + cpc - 1) / cpc;

    roi_pool_fused<<<grid, 256>>>(img, roi, out, totalCells, cpc);
}

// round 15
// speedup vs baseline: 1.0713x; 1.0713x over previous
#include <cuda_runtime.h>

// image [1,128,128,512] f32 NHWC, RoI [N,4] f32 (cx,cy,w,h), POOL=7, STRIDE=16.
#define POOL    7
#define HH      128
#define WW      128
#define CC      512
#define NMAX    1024
#define CPC_MAX 96          // max cells per CTA chunk (smem: 96*32B = 3KB)

// Pinned vector load: asm volatile cannot be sunk/reordered by ptxas, and its
// outputs are forcibly live -> the register double-buffer survives compilation
// (every prior round ptxas collapsed it: regs 35-48 instead of ~60).
__device__ __forceinline__ float4 ldg_pin(const float4* p)
{
    float4 v;
    asm volatile("ld.global.nc.v4.f32 {%0,%1,%2,%3}, [%4];"
                 : "=f"(v.x), "=f"(v.y), "=f"(v.z), "=f"(v.w)
                 : "l"(p));
    return v;
}

// ---------------------------------------------------------------------------
// Single fused kernel, one wave of persistent CTAs (148 x 4 = 592).
//   Phase A: threads 0..cpc-1 compute their cell's bilinear params from the
//            RoI table into smem (math identical to reference).
//   Phase B: register double-buffer with PINNED loads: issue next cell's 4
//            corner LDG.128 (asm volatile, cannot be sunk), then blend+store
//            the current cell's loads from the previous iteration. The
//            consume never waits on freshly issued loads.
// ---------------------------------------------------------------------------
__global__ __launch_bounds__(256, 4)
void roi_pool_fused(const float* __restrict__ img, const float* __restrict__ roi,
                    float* __restrict__ out, int totalCells, int cpc)
{
    __shared__ int4   s_off[CPC_MAX];   // corner offsets, float4 units
    __shared__ float4 s_w  [CPC_MAX];   // bilinear weights

    const int base = blockIdx.x * cpc;
    const int tid  = threadIdx.x;

    if (base >= totalCells) return;

    // ---------------- Phase A: per-cell params into smem ----------------
    if (tid < cpc) {
        int cell = base + tid;
        if (cell < totalCells) {
            int n   = cell / (POOL * POOL);
            int rem = cell - n * (POOL * POOL);
            int py  = rem / POOL;
            int px  = rem - py * POOL;

            const float inv_stride = 1.0f / 16.0f;
            float cx = roi[n * 4 + 0];
            float cy = roi[n * 4 + 1];
            float w  = roi[n * 4 + 2];
            float h  = roi[n * 4 + 3];

            float r  = rintf((cx - 0.5f * w) * inv_stride);   // x start (col)
            float c  = rintf((cy - 0.5f * h) * inv_stride);   // y start (row)
            float wq = fmaxf(rintf(w * inv_stride), 1.0f);
            float hq = fmaxf(rintf(h * inv_stride), 1.0f);

            // y axis (rows, limit HH)
            float gy  = (py + 0.5f) / (float)POOL;
            float sy  = fminf(fmaxf(gy * hq - 0.5f, 0.0f), hq - 1.0f);
            float fy0 = floorf(sy);
            float ly  = sy - fy0;
            float fy1 = fminf(fy0 + 1.0f, hq - 1.0f);
            int iy0 = (int)fminf(fmaxf(c + fy0, 0.0f), (float)(HH - 1));
            int iy1 = (int)fminf(fmaxf(c + fy1, 0.0f), (float)(HH - 1));

            // x axis (cols, limit WW)
            float gx  = (px + 0.5f) / (float)POOL;
            float sx  = fminf(fmaxf(gx * wq - 0.5f, 0.0f), wq - 1.0f);
            float fx0 = floorf(sx);
            float lx  = sx - fx0;
            float fx1 = fminf(fx0 + 1.0f, wq - 1.0f);
            int ix0 = (int)fminf(fmaxf(r + fx0, 0.0f), (float)(WW - 1));
            int ix1 = (int)fminf(fmaxf(r + fx1, 0.0f), (float)(WW - 1));

            s_off[tid] = make_int4((iy0 * WW + ix0) * (CC / 4),
                                   (iy0 * WW + ix1) * (CC / 4),
                                   (iy1 * WW + ix0) * (CC / 4),
                                   (iy1 * WW + ix1) * (CC / 4));
            s_w[tid] = make_float4((1.0f - ly) * (1.0f - lx),
                                   (1.0f - ly) * lx,
                                   ly * (1.0f - lx),
                                   ly * lx);
        }
    }
    __syncthreads();

    // ---------------- Phase B: pinned double-buffered sweep ----------------
    const int lane = tid & 127;         // float4 lane within cell
    const int half = tid >> 7;          // which of 2 interleaved cells

    int nIter = totalCells - base;
    if (nIter > cpc) nIter = cpc;

    const float4* __restrict__ img4 = (const float4*)img;
    float4*       __restrict__ out4 = (float4*)out;

    int i = half;
    if (i >= nIter) return;

    // Prime: params + pinned data loads for first owned cell.
    int4   o0 = s_off[i];
    float4 w0 = s_w[i];
    float4 a0 = ldg_pin(img4 + o0.x + lane);
    float4 b0 = ldg_pin(img4 + o0.y + lane);
    float4 c0 = ldg_pin(img4 + o0.z + lane);
    float4 d0 = ldg_pin(img4 + o0.w + lane);

    while (true) {
        int  nx   = i + 2;
        bool more = nx < nIter;

        // Issue NEXT cell's loads first (pinned: ptxas cannot sink them).
        int4   o1 = o0;
        float4 w1 = w0;
        float4 a1, b1, c1, d1;
        if (more) {
            o1 = s_off[nx];
            w1 = s_w[nx];
            a1 = ldg_pin(img4 + o1.x + lane);
            b1 = ldg_pin(img4 + o1.y + lane);
            c1 = ldg_pin(img4 + o1.z + lane);
            d1 = ldg_pin(img4 + o1.w + lane);
        } else {
            a1 = a0; b1 = b0; c1 = c0; d1 = d0;
        }

        // Consume CURRENT cell (loads issued one full iteration ago).
        float4 r;
        r.x = w0.x * a0.x + w0.y * b0.x + w0.z * c0.x + w0.w * d0.x;
        r.y = w0.x * a0.y + w0.y * b0.y + w0.z * c0.y + w0.w * d0.y;
        r.z = w0.x * a0.z + w0.y * b0.z + w0.z * c0.z + w0.w * d0.z;
        r.w = w0.x * a0.w + w0.y * b0.w + w0.z * c0.w + w0.w * d0.w;

        __stcs(out4 + (size_t)(base + i) * (CC / 4) + lane, r);

        if (!more) break;
        i = nx;
        o0 = o1; w0 = w1;
        a0 = a1; b0 = b1; c0 = c1; d0 = d1;
    }
}

extern "C" void kernel_launch(void* const* d_in, const int* in_sizes, int n_in,
                              void* d_out, int out_size)
{
    const float* img = (const float*)d_in[0];   // [1,128,128,512] f32
    const float* roi = (const float*)d_in[1];   // [N,4] f32
    float*       out = (float*)d_out;           // [1,N,7,7,512] f32

    int N = in_sizes[1] / 4;
    if (N > NMAX) N = NMAX;
    int totalCells = N * POOL * POOL;

    int wave = 148 * 4;                          // one wave at occ=4 (R13 best)
    int cpc  = (totalCells + wave - 1) / wave;   // cells per CTA chunk
    if (cpc > CPC_MAX) cpc = CPC_MAX;
    int grid = (totalCells + cpc - 1) / cpc;

    roi_pool_fused<<<grid, 256>>>(img, roi, out, totalCells, cpc);
}